// round 6
// baseline (speedup 1.0000x reference)
#include <cuda_runtime.h>
#include <cuda_bf16.h>

// ODEfunc: dy = tanh(y@W1 + t*wt + b1) @ W2 + b2 ; div_i = sum_h sech2(z_h)*c_h
// with c_h = sum_d W1[d,h]*W2[h,d]  (analytic trace of the Jacobian).
// Output: [N, D+1] = [dy | -div]
//
// Main loop: packed f32x2 FMA (2 IEEE-rn FMAs per issue) -> FMA-pipe bound.
// Prologue: conflict-free two-step smem transpose of W1.
// Epilogue: single-pass parallel reduction (STS.128) reusing the W1T smem region.
// tanh: u = 2*rcp(exp(2z)+1); a = 1-u; sech2 = u*(2-u)  (exact limits at +-inf).

#define N_SAMP 8192
#define D_DIM  64
#define H_DIM  256

#define SAMP_PER_BLK 64
#define WSTRIDE 68     // floats; 272B rows -> 16B aligned, conflict-free row reads
#define TSTRIDE 260    // scratch transpose tile row stride (floats), 16B aligned

typedef unsigned long long ull;

__device__ __forceinline__ ull pack2(float lo, float hi) {
    ull r; asm("mov.b64 %0, {%1, %2};" : "=l"(r) : "f"(lo), "f"(hi)); return r;
}
__device__ __forceinline__ void unpack2(ull v, float& lo, float& hi) {
    asm("mov.b64 {%0, %1}, %2;" : "=f"(lo), "=f"(hi) : "l"(v));
}
__device__ __forceinline__ float rcp_approx(float x) {
    float r; asm("rcp.approx.f32 %0, %1;" : "=f"(r) : "f"(x)); return r;
}
#define FMA2(d, a, b, c) asm("fma.rn.f32x2 %0, %1, %2, %3;" : "=l"(d) : "l"(a), "l"(b), "l"(c))

__global__ void __launch_bounds__(256, 1)
ode_fused_kernel(const float* __restrict__ t_in,
                 const float* __restrict__ y_g,
                 const float* __restrict__ W1_g,   // [D, H] row-major
                 const float* __restrict__ b1_g,   // [H]
                 const float* __restrict__ wt_g,   // [H]
                 const float* __restrict__ W2_g,   // [H, D] row-major
                 const float* __restrict__ b2_g,   // [D]
                 float* __restrict__ out)          // [N, D+1]
{
    extern __shared__ float sm[];
    float*  W1T   = sm;                          // [H][WSTRIDE]; later reused as P partial tile
    float*  W2s   = W1T + H_DIM * WSTRIDE;       // [H][WSTRIDE]; first used as transpose scratch T
    float2* metas = (float2*)(W2s + H_DIM * WSTRIDE); // [H] : {t*wt+b1, c_h}
    float*  b2s   = (float*)(metas + H_DIM);     // [D]
    float*  T     = W2s;                         // scratch: [D][TSTRIDE]

    const int tid  = threadIdx.x;
    const int lane = tid & 31;
    const int wid  = tid >> 5;
    const int q    = wid & 3;    // h-chunk 0..3
    const int set  = wid >> 2;   // sample set 0/1
    const int sloc = set * 32 + lane;                    // local sample 0..63
    const int sg   = blockIdx.x * SAMP_PER_BLK + sloc;   // global sample

    const float t = t_in[0];

    // ---- load y (packed pairs) early; overlaps with smem staging ----
    ull yp[32];
    {
        const ulonglong2* yv = (const ulonglong2*)(y_g + sg * D_DIM);
        #pragma unroll
        for (int i = 0; i < 16; i++) {
            ulonglong2 v = yv[i];
            yp[2*i+0] = v.x; yp[2*i+1] = v.y;
        }
    }

    // ---- Step A: W1 [k][h] -> scratch T[k][h] (coalesced LDG.128, conflict-free STS.128) ----
    {
        const float4* w1v = (const float4*)W1_g;
        #pragma unroll
        for (int j = 0; j < 16; j++) {
            int v  = tid + 256 * j;     // float4 index, 0..4095
            int k  = v >> 6;            // 0..63
            int hq = v & 63;            // float4 within row
            *(float4*)(T + k * TSTRIDE + 4 * hq) = w1v[v];
        }
    }
    __syncthreads();

    // ---- Step B: transpose T -> W1T[h][k] (stride-1 LDS reads, conflict-free STS.128) ----
    {
        const int h = tid;              // each thread owns one output row
        #pragma unroll
        for (int j = 0; j < 16; j++) {  // k-quad
            float4 r;
            r.x = T[(4*j + 0) * TSTRIDE + h];
            r.y = T[(4*j + 1) * TSTRIDE + h];
            r.z = T[(4*j + 2) * TSTRIDE + h];
            r.w = T[(4*j + 3) * TSTRIDE + h];
            *(float4*)(W1T + h * WSTRIDE + 4*j) = r;
        }
    }
    __syncthreads();   // T reads done -> safe to overwrite with W2s

    // ---- W2 [h][d] -> W2s[h][d] (coalesced LDG.128, conflict-free STS.128) ----
    {
        const float4* w2v = (const float4*)W2_g;
        #pragma unroll
        for (int j = 0; j < 16; j++) {
            int v  = tid + 256 * j;     // float4 index, 0..4095
            int h  = v >> 4;
            int dq = v & 15;
            *(float4*)(W2s + h * WSTRIDE + 4 * dq) = w2v[v];
        }
        if (tid < D_DIM) b2s[tid] = b2_g[tid];
    }
    __syncthreads();

    // ---- per-h meta: bias (t*wt+b1) and Jacobian-trace weight c_h ----
    {
        int h = tid; // 256 threads == H
        const float4* u4 = (const float4*)(W1T + h * WSTRIDE);
        const float4* v4 = (const float4*)(W2s + h * WSTRIDE);
        float ca = 0.f, cb = 0.f, cc = 0.f, cd = 0.f;
        #pragma unroll
        for (int k = 0; k < 16; k++) {
            float4 u = u4[k], v = v4[k];
            ca += u.x * v.x; cb += u.y * v.y; cc += u.z * v.z; cd += u.w * v.w;
        }
        metas[h] = make_float2(fmaf(t, wt_g[h], b1_g[h]), (ca + cb) + (cc + cd));
    }
    __syncthreads();

    // ---- main fused loop over this warp's 64 h values (packed f32x2) ----
    ull dyp[32];
    #pragma unroll
    for (int d = 0; d < 32; d++) dyp[d] = 0ull;
    float divacc = 0.f;

    const int h0 = q * 64;
    for (int hh = 0; hh < 64; hh++) {
        const int h = h0 + hh;
        const ulonglong2* w1r = (const ulonglong2*)(W1T + h * WSTRIDE);

        // z = y . W1[:,h] : 32 packed FMAs over 4 accumulator chains
        ull zp0 = 0ull, zp1 = 0ull, zp2 = 0ull, zp3 = 0ull;
        #pragma unroll
        for (int k = 0; k < 8; k++) {
            ulonglong2 wa = w1r[2*k];
            ulonglong2 wb = w1r[2*k+1];
            FMA2(zp0, yp[4*k+0], wa.x, zp0);
            FMA2(zp1, yp[4*k+1], wa.y, zp1);
            FMA2(zp2, yp[4*k+2], wb.x, zp2);
            FMA2(zp3, yp[4*k+3], wb.y, zp3);
        }
        float a0,a1,b0,b1,c0,c1,d0,d1;
        unpack2(zp0, a0, a1); unpack2(zp1, b0, b1);
        unpack2(zp2, c0, c1); unpack2(zp3, d0, d1);
        float2 m = metas[h];
        float z = (((a0+a1)+(b0+b1)) + ((c0+c1)+(d0+d1))) + m.x;

        // tanh + sech^2 via exp: e = exp(2z); u = 2*rcp(e+1); a = 1-u; sech2 = u*(2-u)
        float e = __expf(2.0f * z);
        float u = 2.0f * rcp_approx(e + 1.0f);
        float a = 1.0f - u;

        divacc = fmaf(u * (2.0f - u), m.y, divacc);

        // dy += a * W2[h,:] : 32 packed FMAs
        ull aa = pack2(a, a);
        const ulonglong2* w2r = (const ulonglong2*)(W2s + h * WSTRIDE);
        #pragma unroll
        for (int k = 0; k < 16; k++) {
            ulonglong2 w = w2r[k];
            FMA2(dyp[2*k+0], aa, w.x, dyp[2*k+0]);
            FMA2(dyp[2*k+1], aa, w.y, dyp[2*k+1]);
        }
    }

    // ---- parallel epilogue: 4 partials written concurrently into P (reuses W1T), one gather ----
    float* P = W1T;   // rows: row = q*64 + sloc, cols 0..63 = dy, col 64 = -div
    __syncthreads();  // all W1T reads complete before overwrite
    {
        // 272B row base -> 16B aligned: write partials as STS.128
        ulonglong2* Prow = (ulonglong2*)(P + (q * 64 + sloc) * WSTRIDE);
        #pragma unroll
        for (int d = 0; d < 16; d++) {
            ulonglong2 v; v.x = dyp[2*d]; v.y = dyp[2*d+1];
            Prow[d] = v;
        }
        ((float*)Prow)[64] = -divacc;
    }
    __syncthreads();

    // gather: out[s][d] = sum_q P[q][s][d] (+ b2[d] for d<64), coalesced store
    {
        float* outp = out + (size_t)blockIdx.x * SAMP_PER_BLK * (D_DIM + 1);
        for (int i = tid; i < SAMP_PER_BLK * (D_DIM + 1); i += 256) {
            int s = i / (D_DIM + 1);
            int d = i - s * (D_DIM + 1);
            const float* col = P + s * WSTRIDE + d;
            float v = (col[0] + col[64 * WSTRIDE])
                    + (col[128 * WSTRIDE] + col[192 * WSTRIDE]);
            if (d < D_DIM) v += b2s[d];
            outp[i] = v;
        }
    }
}

extern "C" void kernel_launch(void* const* d_in, const int* in_sizes, int n_in,
                              void* d_out, int out_size)
{
    const float* t  = (const float*)d_in[0];
    const float* y  = (const float*)d_in[1];
    const float* W1 = (const float*)d_in[2];
    const float* b1 = (const float*)d_in[3];
    const float* wt = (const float*)d_in[4];
    const float* W2 = (const float*)d_in[5];
    const float* b2 = (const float*)d_in[6];
    float* out = (float*)d_out;

    const int smem_bytes =
        (H_DIM * WSTRIDE * 2) * 4      // W1T + W2s (W2s region doubles as transpose scratch)
        + H_DIM * 8                    // metas (float2)
        + D_DIM * 4;                   // b2

    cudaFuncSetAttribute(ode_fused_kernel,
                         cudaFuncAttributeMaxDynamicSharedMemorySize, smem_bytes);

    dim3 grid(N_SAMP / SAMP_PER_BLK);   // 128
    dim3 block(256);
    ode_fused_kernel<<<grid, block, smem_bytes>>>(t, y, W1, b1, wt, W2, b2, out);
}